// round 16
// baseline (speedup 1.0000x reference)
#include <cuda_runtime.h>
#include <cuda_bf16.h>
#include <cstdint>
#include <math.h>

// Problem constants
#define BB 2048
#define DD 4096
#define PP 64
#define EE 8
#define KK 64
#define TWO_C 128

#define WROW 72               // padded row stride in bf16 (144 B)
#define WROWB 144
#define BUFB (PP * WROWB)     // one B tile: 9216 B

#define TPB 8                 // batch elements per block
#define NBLK (BB / TPB)       // 256 blocks
#define NTHR 512              // 16 warps

// dynamic smem layout (everything dynamic; zero static smem)
#define SM_A    0                        // A tile: 18432 B (aliased w/ sacc pre-GEMM)
#define SM_B    18432                    // 8 B tiles: 73728 B
#define SM_BIAS (18432 + TPB * BUFB)     // 92160: 128 floats = 512 B
#define SM_WRED (SM_BIAS + 512)          // 92672: TPB*16 floats = 512 B
#define SM_IDX  (SM_WRED + 512)          // 93184: TPB ints = 32 B
#define SM_GATE (SM_IDX + 32)            // 93216: TPB floats = 32 B
#define SM_TOTAL (SM_GATE + 32)          // 93248 B -> 2 blocks/SM = 186.5 KB

// loss accumulators (deterministic fixed-point; self-resetting per launch)
__device__ unsigned long long g_lsum[EE];
__device__ int                g_cnt[EE];
__device__ unsigned int       g_ticket;

// ---------------- helpers ----------------
__device__ __forceinline__ uint32_t smem_u32(const void* p) {
    uint32_t a;
    asm("{ .reg .u64 t; cvta.to.shared.u64 t, %1; cvt.u32.u64 %0, t; }" : "=r"(a) : "l"(p));
    return a;
}
__device__ __forceinline__ void ldsm_x4(uint32_t& r0, uint32_t& r1, uint32_t& r2, uint32_t& r3,
                                        uint32_t addr) {
    asm volatile("ldmatrix.sync.aligned.m8n8.x4.shared.b16 {%0,%1,%2,%3}, [%4];"
                 : "=r"(r0), "=r"(r1), "=r"(r2), "=r"(r3) : "r"(addr));
}
__device__ __forceinline__ void mma_bf16(float* d, const uint32_t* a, uint32_t b0, uint32_t b1) {
    asm volatile(
        "mma.sync.aligned.m16n8k16.row.col.f32.bf16.bf16.f32 "
        "{%0,%1,%2,%3}, {%4,%5,%6,%7}, {%8,%9}, {%0,%1,%2,%3};"
        : "+f"(d[0]), "+f"(d[1]), "+f"(d[2]), "+f"(d[3])
        : "r"(a[0]), "r"(a[1]), "r"(a[2]), "r"(a[3]), "r"(b0), "r"(b1));
}
__device__ __forceinline__ uint32_t pack_bf16x2(float lo, float hi) {
    __nv_bfloat162 h = __float22bfloat162_rn(make_float2(lo, hi));
    return *(uint32_t*)&h;
}
__device__ __forceinline__ void cmpswap(int& a, int& b) {
    int lo = min(a, b), hi = max(a, b);
    a = lo; b = hi;
}

// ---------------------------------------------------------------------------
// ONE fused kernel. Block = 8 batch elements, 512 threads, 2 blocks/SM,
// exactly one wave (256 blocks <= 296 slots).
// ---------------------------------------------------------------------------
__global__ __launch_bounds__(NTHR, 2) void moe_one(
    const float* __restrict__ x,
    const float* __restrict__ rw,
    const float* __restrict__ ew,
    const float* __restrict__ eb,
    float* __restrict__ out,
    int full)
{
    extern __shared__ __align__(16) char dsm[];
    __nv_bfloat16* asm_w = (__nv_bfloat16*)(dsm + SM_A);
    __nv_bfloat16* bsm   = (__nv_bfloat16*)(dsm + SM_B);
    float* bias_s        = (float*)(dsm + SM_BIAS);
    float (*wred)[16]    = (float(*)[16])(dsm + SM_WRED);
    int*   s_idx         = (int*)(dsm + SM_IDX);
    float* s_gate        = (float*)(dsm + SM_GATE);
    float4 (*sacc)[16]   = (float4(*)[16])(dsm + SM_A);   // alias: dead before weights staged

    const int t = threadIdx.x;
    const int wid = t >> 5, lid = t & 31;
    const int jb = wid >> 1;          // local b (0..7), one warp-pair each
    const int h  = wid & 1;           // which half of x[b]
    const int b  = blockIdx.x * TPB + jb;

    // ---- phase 1: load x[b] half (4 batches of 4 float4), fp32 partials + bf16 tile
    const float4* xb4 = (const float4*)(x + (size_t)b * DD);
    __nv_bfloat16* myb = bsm + jb * (PP * WROW);
    float4 acc = make_float4(0.f, 0.f, 0.f, 0.f);
    const int kq = lid & 15;

    #pragma unroll
    for (int ch = 0; ch < 4; ch++) {
        float4 v[4];
        #pragma unroll
        for (int i = 0; i < 4; i++)
            v[i] = xb4[lid + ((ch * 4 + i) << 5) + (h << 9)];
        #pragma unroll
        for (int i = 0; i < 4; i++) {
            acc.x += v[i].x; acc.y += v[i].y; acc.z += v[i].z; acc.w += v[i].w;
            const int p = (lid >> 4) + ((ch * 4 + i) << 1) + (h << 5);
            uint2 pk;
            pk.x = pack_bf16x2(v[i].x, v[i].y);
            pk.y = pack_bf16x2(v[i].z, v[i].w);
            *(uint2*)(myb + p * WROW + (kq << 2)) = pk;
        }
    }
    acc.x += __shfl_xor_sync(0xffffffffu, acc.x, 16);
    acc.y += __shfl_xor_sync(0xffffffffu, acc.y, 16);
    acc.z += __shfl_xor_sync(0xffffffffu, acc.z, 16);
    acc.w += __shfl_xor_sync(0xffffffffu, acc.w, 16);
    if (h == 1 && lid < 16) sacc[jb][lid] = acc;
    __syncthreads();                                    // S1: tiles + partials ready

    // ---- phase 2: routers on even warps (h==0), one per b
    if (h == 0) {
        float4 o = sacc[jb][kq];
        acc.x += o.x; acc.y += o.y; acc.z += o.z; acc.w += o.w;

        const float4* rw4 = (const float4*)rw;
        float mysel = 0.f;                 // lane e keeps sel[e]
        float g = -1e30f; int idx = 0;
        #pragma unroll
        for (int e = 0; e < EE; e++) {
            float4 w = rw4[e * 16 + kq];
            float p = acc.x * w.x + acc.y * w.y + acc.z * w.z + acc.w * w.w;
            p += __shfl_xor_sync(0xffffffffu, p, 8);
            p += __shfl_xor_sync(0xffffffffu, p, 4);
            p += __shfl_xor_sync(0xffffffffu, p, 2);
            p += __shfl_xor_sync(0xffffffffu, p, 1);
            if (lid == e) mysel = p;
            if (p > g) { g = p; idx = e; }
        }
        if (lid == 0) {
            s_idx[jb] = idx; s_gate[jb] = g;
            atomicAdd(&g_cnt[idx], 1);
        }
        if (lid < EE) {
            long long q = llrint((double)mysel * 4294967296.0);
            atomicAdd(&g_lsum[lid], (unsigned long long)q);
            if (full)
                out[BB * 2 + b * EE + lid] = (lid == idx && g != 0.f) ? 1.f : 0.f;
        }
    }
    __syncthreads();                                    // S2: routing visible; sacc dead

    // ---- phase 3: sort 8 tasks by expert (key = e*8 + tile; distinct)
    int k[TPB];
    #pragma unroll
    for (int i = 0; i < TPB; i++) k[i] = s_idx[i] * TPB + i;
    // Batcher 8-element sorting network (19 comparators)
    cmpswap(k[0],k[1]); cmpswap(k[2],k[3]); cmpswap(k[4],k[5]); cmpswap(k[6],k[7]);
    cmpswap(k[0],k[2]); cmpswap(k[1],k[3]); cmpswap(k[4],k[6]); cmpswap(k[5],k[7]);
    cmpswap(k[1],k[2]); cmpswap(k[5],k[6]);
    cmpswap(k[0],k[4]); cmpswap(k[1],k[5]); cmpswap(k[2],k[6]); cmpswap(k[3],k[7]);
    cmpswap(k[2],k[4]); cmpswap(k[3],k[5]);
    cmpswap(k[1],k[2]); cmpswap(k[3],k[4]); cmpswap(k[5],k[6]);

    const int cw = wid & 3;           // c-group (0..3): rows 32*cw..+31
    const int pw = wid >> 2;          // p-group (0..3): p 16*pw..+15
    const uint32_t Abase = smem_u32(asm_w);
    const uint32_t Bbase = smem_u32(bsm);
    const uint32_t a_addr = Abase + (uint32_t)(((cw << 5) + (lid & 15)) * WROWB + ((lid >> 4) << 4));
    const uint32_t b_off  = (uint32_t)(((pw << 4) + (lid & 7) + ((lid >> 4) << 3)) * WROWB
                                       + (((lid >> 3) & 1) << 4));
    int e_cur = -1;

    #pragma unroll
    for (int it = 0; it < TPB; it++) {
        const int key  = k[it];
        const int e    = key >> 3;
        const int tile = key & 7;

        if (e != e_cur) {                                // block-uniform
            if (e_cur >= 0) __syncthreads();             // protect old asm_w reads
            e_cur = e;
            const float4* src = (const float4*)(ew + (size_t)e * (TWO_C * KK));
            #pragma unroll
            for (int i = 0; i < 4; i++) {
                int idx4 = (i << 9) + t;                 // row = idx4>>4, ch = idx4&15
                float4 v = src[idx4];
                uint2 pk;
                pk.x = pack_bf16x2(v.x, v.y);
                pk.y = pack_bf16x2(v.z, v.w);
                *(uint2*)&asm_w[(idx4 >> 4) * WROW + ((idx4 & 15) << 2)] = pk;
            }
            if (t < TWO_C) bias_s[t] = eb[e * TWO_C + t];
            __syncthreads();
        }

        // ---- GEMM on tile: warp covers 32c x 16p; A+B fragments loaded per ks
        const uint32_t b_base = Bbase + (uint32_t)(tile * BUFB) + b_off;
        float accv[2][2][4];
        #pragma unroll
        for (int m = 0; m < 2; m++)
            #pragma unroll
            for (int n = 0; n < 2; n++)
                #pragma unroll
                for (int i = 0; i < 4; i++) accv[m][n][i] = 0.f;

        #pragma unroll
        for (int ks = 0; ks < 4; ks++) {
            uint32_t a0[4], a1[4];
            ldsm_x4(a0[0], a0[1], a0[2], a0[3], a_addr + ks * 32);
            ldsm_x4(a1[0], a1[1], a1[2], a1[3], a_addr + 16 * WROWB + ks * 32);
            uint32_t r0, r1, r2, r3;
            ldsm_x4(r0, r1, r2, r3, b_base + ks * 32);
            mma_bf16(accv[0][0], a0, r0, r1);
            mma_bf16(accv[0][1], a0, r2, r3);
            mma_bf16(accv[1][0], a1, r0, r1);
            mma_bf16(accv[1][1], a1, r2, r3);
        }

        float part = 0.f;
        #pragma unroll
        for (int m = 0; m < 2; m++) {
            const float bv1 = bias_s[(cw << 5) + (m << 4) + (lid >> 2)];
            const float bv2 = bias_s[(cw << 5) + (m << 4) + (lid >> 2) + 8];
            #pragma unroll
            for (int n = 0; n < 2; n++) {
                float z0 = accv[m][n][0] + bv1;
                float z1 = accv[m][n][1] + bv1;
                float z2 = accv[m][n][2] + bv2;
                float z3 = accv[m][n][3] + bv2;
                part += z0 * z0 * z0 + z1 * z1 * z1 + z2 * z2 * z2 + z3 * z3 * z3;
            }
        }
        #pragma unroll
        for (int o = 16; o > 0; o >>= 1)
            part += __shfl_xor_sync(0xffffffffu, part, o);
        if (lid == 0) wred[it][wid] = part;
    }

    __syncthreads();                                    // S-final

    // ---- phase 4: 8 softmaxes in parallel (threads 0..7)
    if (t < TPB) {
        const int key  = k[t];
        const int tile = key & 7;
        float v0 = 0.f, v1 = 0.f;
        #pragma unroll
        for (int w = 0; w < 16; w++) {
            if ((w & 3) < 2) v0 += wred[t][w];          // c in [0,64)
            else             v1 += wred[t][w];          // c in [64,128)
        }
        float gate = s_gate[tile];
        float a0v = gate * v0, a1v = gate * v1;
        float m  = fmaxf(a0v, a1v);
        float e0 = expf(a0v - m), e1 = expf(a1v - m);
        float inv = 1.f / (e0 + e1);
        const int bo = blockIdx.x * TPB + tile;
        out[bo * 2 + 0] = e0 * inv;
        out[bo * 2 + 1] = e1 * inv;
    }

    // ---- loss finalization (last block), off everyone else's path
    if (t == 32) {
        __threadfence();
        unsigned int tk = atomicAdd(&g_ticket, 1u);
        if (tk == NBLK - 1) {
            __threadfence();
            double L = 0.0;
            #pragma unroll
            for (int e = 0; e < EE; e++) {
                unsigned long long sraw = atomicAdd(&g_lsum[e], 0ULL);
                int cc = atomicAdd(&g_cnt[e], 0);
                L += ((double)(long long)sraw * (1.0 / 4294967296.0)) * (double)cc;
            }
            if (full)
                out[BB * 2 + BB * EE] = (float)(L * (double)EE / ((double)BB * (double)BB));
            #pragma unroll
            for (int e = 0; e < EE; e++) {
                atomicExch(&g_lsum[e], 0ULL);
                atomicExch(&g_cnt[e], 0);
            }
            atomicExch(&g_ticket, 0u);
        }
    }
}

// ---------------------------------------------------------------------------
extern "C" void kernel_launch(void* const* d_in, const int* in_sizes, int n_in,
                              void* d_out, int out_size)
{
    const float* x  = (const float*)d_in[0];
    const float* rw = (const float*)d_in[1];
    const float* ew = (const float*)d_in[2];
    const float* eb = (const float*)d_in[3];
    float* out = (float*)d_out;

    const int full = (out_size >= BB * 2 + BB * EE + 1) ? 1 : 0;

    cudaFuncSetAttribute(moe_one, cudaFuncAttributeMaxDynamicSharedMemorySize, SM_TOTAL);
    cudaFuncSetAttribute(moe_one, cudaFuncAttributePreferredSharedMemoryCarveout, 100);
    moe_one<<<NBLK, NTHR, SM_TOTAL>>>(x, rw, ew, eb, out, full);
}

// round 17
// speedup vs baseline: 1.1061x; 1.1061x over previous
#include <cuda_runtime.h>
#include <cuda_bf16.h>
#include <cstdint>
#include <math.h>

// Problem constants
#define BB 2048
#define DD 4096
#define PP 64
#define EE 8
#define KK 64
#define TWO_C 128

#define WROW 72               // padded row stride in bf16 (144 B)
#define WROWB 144
#define BUFB (PP * WROW * 2)  // one B tile: 9216 B

#define TPB 2                 // batch elements per block
#define NBLK (BB / TPB)       // 1024 blocks
#define NTHR 256              // 8 warps

// dynamic smem layout (zero static smem)
#define SM_STAGE 0                       // fp32 x stage: 2 * 16384 = 32768 B
                                         // A tile (18432 B) aliases at 0 after routing
#define SM_B     32768                   // 2 B tiles: 18432 B
#define SM_BIAS  (32768 + 18432)         // 51200: 128 floats = 512 B
#define SM_SACC  (SM_BIAS + 512)         // 51712: 8 warps x 16 float4 = 2048 B
#define SM_WRED  (SM_SACC + 2048)        // 53760: 2*8 floats = 64 B
#define SM_IDX   (SM_WRED + 64)          // 53824: 2 ints
#define SM_GATE  (SM_IDX + 8)            // 53832: 2 floats
#define SM_TOTAL (SM_GATE + 8)           // 53840 B -> 4 blocks/SM = 210.3 KB

// loss accumulators (deterministic fixed-point; self-resetting per launch)
__device__ unsigned long long g_lsum[EE];
__device__ int                g_cnt[EE];
__device__ unsigned int       g_ticket;

// ---------------- helpers ----------------
__device__ __forceinline__ uint32_t smem_u32(const void* p) {
    uint32_t a;
    asm("{ .reg .u64 t; cvta.to.shared.u64 t, %1; cvt.u32.u64 %0, t; }" : "=r"(a) : "l"(p));
    return a;
}
__device__ __forceinline__ void ldsm_x4(uint32_t& r0, uint32_t& r1, uint32_t& r2, uint32_t& r3,
                                        uint32_t addr) {
    asm volatile("ldmatrix.sync.aligned.m8n8.x4.shared.b16 {%0,%1,%2,%3}, [%4];"
                 : "=r"(r0), "=r"(r1), "=r"(r2), "=r"(r3) : "r"(addr));
}
__device__ __forceinline__ void mma_bf16(float* d, const uint32_t* a, uint32_t b0, uint32_t b1) {
    asm volatile(
        "mma.sync.aligned.m16n8k16.row.col.f32.bf16.bf16.f32 "
        "{%0,%1,%2,%3}, {%4,%5,%6,%7}, {%8,%9}, {%0,%1,%2,%3};"
        : "+f"(d[0]), "+f"(d[1]), "+f"(d[2]), "+f"(d[3])
        : "r"(a[0]), "r"(a[1]), "r"(a[2]), "r"(a[3]), "r"(b0), "r"(b1));
}
__device__ __forceinline__ uint32_t pack_bf16x2(float lo, float hi) {
    __nv_bfloat162 h = __float22bfloat162_rn(make_float2(lo, hi));
    return *(uint32_t*)&h;
}
__device__ __forceinline__ void cp_async16(uint32_t smem_addr, const void* gmem) {
    asm volatile("cp.async.cg.shared.global [%0], [%1], 16;" :: "r"(smem_addr), "l"(gmem));
}
__device__ __forceinline__ void cmpswap(int& a, int& b) {
    int lo = min(a, b), hi = max(a, b);
    a = lo; b = hi;
}

// ---------------------------------------------------------------------------
// ONE fused kernel. Block = 2 batch elements, 256 threads, 4 blocks/SM.
// Phase 1 uses cp.async: one DRAM round-trip for all 32 KB of x per block.
// ---------------------------------------------------------------------------
__global__ __launch_bounds__(NTHR, 4) void moe_one(
    const float* __restrict__ x,
    const float* __restrict__ rw,
    const float* __restrict__ ew,
    const float* __restrict__ eb,
    float* __restrict__ out,
    int full)
{
    extern __shared__ __align__(16) char dsm[];
    float*         xstage = (float*)(dsm + SM_STAGE);            // 2 b x 4096 fp32
    __nv_bfloat16* asm_w  = (__nv_bfloat16*)(dsm + SM_STAGE);    // alias (post-routing)
    __nv_bfloat16* bsm    = (__nv_bfloat16*)(dsm + SM_B);
    float*         bias_s = (float*)(dsm + SM_BIAS);
    float4 (*sacc)[16]    = (float4(*)[16])(dsm + SM_SACC);
    float (*wred)[8]      = (float(*)[8])(dsm + SM_WRED);
    int*   s_idx          = (int*)(dsm + SM_IDX);
    float* s_gate         = (float*)(dsm + SM_GATE);

    const int t = threadIdx.x;
    const int wid = t >> 5, lid = t & 31;

    // ---- phase 1a: cp.async the whole block's x (2048 16B chunks, 8/thread)
    {
        const char* src = (const char*)(x + (size_t)blockIdx.x * TPB * DD);
        const uint32_t dst = smem_u32(xstage);
        #pragma unroll
        for (int i = 0; i < 8; i++) {
            int ch = t + (i << 8);                 // 0..2047
            cp_async16(dst + (ch << 4), src + (ch << 4));
        }
        asm volatile("cp.async.commit_group;" ::: "memory");
        asm volatile("cp.async.wait_group 0;" ::: "memory");
    }
    __syncthreads();                               // stage visible to all

    // ---- phase 1b: convert fp32 stage -> bf16 tiles + router partial sums
    // 4 warps per b: jb = wid>>2, quarter wq = wid&3
    const int jb = wid >> 2;
    const int wq = wid & 3;
    const int kq = lid & 15;
    {
        const float4* st4 = (const float4*)(xstage + jb * DD);
        __nv_bfloat16* myb = bsm + jb * (PP * WROW);
        float4 acc = make_float4(0.f, 0.f, 0.f, 0.f);
        #pragma unroll
        for (int ch = 0; ch < 2; ch++) {
            float4 v[4];
            #pragma unroll
            for (int i = 0; i < 4; i++)
                v[i] = st4[lid + (((wq << 3) + (ch << 2) + i) << 5)];
            #pragma unroll
            for (int i = 0; i < 4; i++) {
                acc.x += v[i].x; acc.y += v[i].y; acc.z += v[i].z; acc.w += v[i].w;
                const int p = (lid >> 4) + (((wq << 3) + (ch << 2) + i) << 1);
                uint2 pk;
                pk.x = pack_bf16x2(v[i].x, v[i].y);
                pk.y = pack_bf16x2(v[i].z, v[i].w);
                *(uint2*)(myb + p * WROW + (kq << 2)) = pk;
            }
        }
        acc.x += __shfl_xor_sync(0xffffffffu, acc.x, 16);
        acc.y += __shfl_xor_sync(0xffffffffu, acc.y, 16);
        acc.z += __shfl_xor_sync(0xffffffffu, acc.z, 16);
        acc.w += __shfl_xor_sync(0xffffffffu, acc.w, 16);
        if (lid < 16) sacc[wid][lid] = acc;
    }
    __syncthreads();                               // S1: tiles + partials ready

    // ---- phase 2: routers on warps 0 (b0) and 4 (b1)
    if (wq == 0) {
        const int b = blockIdx.x * TPB + jb;
        float4 acc = sacc[wid][kq];
        #pragma unroll
        for (int q = 1; q < 4; q++) {
            float4 o = sacc[wid + q][kq];
            acc.x += o.x; acc.y += o.y; acc.z += o.z; acc.w += o.w;
        }
        const float4* rw4 = (const float4*)rw;
        float mysel = 0.f;
        float g = -1e30f; int idx = 0;
        #pragma unroll
        for (int e = 0; e < EE; e++) {
            float4 w = rw4[e * 16 + kq];
            float p = acc.x * w.x + acc.y * w.y + acc.z * w.z + acc.w * w.w;
            p += __shfl_xor_sync(0xffffffffu, p, 8);
            p += __shfl_xor_sync(0xffffffffu, p, 4);
            p += __shfl_xor_sync(0xffffffffu, p, 2);
            p += __shfl_xor_sync(0xffffffffu, p, 1);
            if (lid == e) mysel = p;
            if (p > g) { g = p; idx = e; }
        }
        if (lid == 0) {
            s_idx[jb] = idx; s_gate[jb] = g;
            atomicAdd(&g_cnt[idx], 1);
        }
        if (lid < EE) {
            long long q = llrint((double)mysel * 4294967296.0);
            atomicAdd(&g_lsum[lid], (unsigned long long)q);
            if (full)
                out[BB * 2 + b * EE + lid] = (lid == idx && g != 0.f) ? 1.f : 0.f;
        }
    }
    __syncthreads();                               // S2: routing visible; stage dead

    // ---- phase 3: sort 2 tasks by expert (key = e*2 + tile; distinct)
    int k0 = s_idx[0] * 2 + 0, k1 = s_idx[1] * 2 + 1;
    cmpswap(k0, k1);

    const int cw = wid & 3;
    const int pw = wid >> 2;
    const uint32_t Abase = smem_u32(asm_w);
    const uint32_t Bbase = smem_u32(bsm);
    const uint32_t a_addr = Abase + (uint32_t)(((cw << 5) + (lid & 15)) * WROWB + ((lid >> 4) << 4));
    const uint32_t b_off  = (uint32_t)(((pw << 5) + (lid & 7) + ((lid >> 4) << 3)) * WROWB
                                       + (((lid >> 3) & 1) << 4));
    int e_cur = -1;

    #pragma unroll
    for (int it = 0; it < TPB; it++) {
        const int key  = (it == 0) ? k0 : k1;
        const int e    = key >> 1;
        const int tile = key & 1;

        if (e != e_cur) {                          // block-uniform
            if (e_cur >= 0) __syncthreads();       // protect old asm_w reads
            e_cur = e;
            const float4* src = (const float4*)(ew + (size_t)e * (TWO_C * KK));
            #pragma unroll
            for (int i = 0; i < 8; i++) {
                int idx4 = (i << 8) + t;           // row = idx4>>4, ch = idx4&15
                float4 v = src[idx4];
                uint2 pk;
                pk.x = pack_bf16x2(v.x, v.y);
                pk.y = pack_bf16x2(v.z, v.w);
                *(uint2*)&asm_w[(idx4 >> 4) * WROW + ((idx4 & 15) << 2)] = pk;
            }
            if (t < TWO_C) bias_s[t] = eb[e * TWO_C + t];
            __syncthreads();
        }

        // ---- GEMM on tile, two p-halves of 16; warp grid 4c x 2p
        const uint32_t b_base = Bbase + (uint32_t)(tile * BUFB) + b_off;
        float part = 0.f;
        #pragma unroll
        for (int hh = 0; hh < 2; hh++) {
            float accv[2][2][4];
            #pragma unroll
            for (int m = 0; m < 2; m++)
                #pragma unroll
                for (int n = 0; n < 2; n++)
                    #pragma unroll
                    for (int i = 0; i < 4; i++) accv[m][n][i] = 0.f;

            #pragma unroll
            for (int ks = 0; ks < 4; ks++) {
                uint32_t a0[4], a1[4];
                ldsm_x4(a0[0], a0[1], a0[2], a0[3], a_addr + ks * 32);
                ldsm_x4(a1[0], a1[1], a1[2], a1[3], a_addr + 16 * WROWB + ks * 32);
                uint32_t r0, r1, r2, r3;
                ldsm_x4(r0, r1, r2, r3, b_base + hh * (16 * WROWB) + ks * 32);
                mma_bf16(accv[0][0], a0, r0, r1);
                mma_bf16(accv[0][1], a0, r2, r3);
                mma_bf16(accv[1][0], a1, r0, r1);
                mma_bf16(accv[1][1], a1, r2, r3);
            }

            #pragma unroll
            for (int m = 0; m < 2; m++) {
                const float bv1 = bias_s[(cw << 5) + (m << 4) + (lid >> 2)];
                const float bv2 = bias_s[(cw << 5) + (m << 4) + (lid >> 2) + 8];
                #pragma unroll
                for (int n = 0; n < 2; n++) {
                    float z0 = accv[m][n][0] + bv1;
                    float z1 = accv[m][n][1] + bv1;
                    float z2 = accv[m][n][2] + bv2;
                    float z3 = accv[m][n][3] + bv2;
                    part += z0 * z0 * z0 + z1 * z1 * z1 + z2 * z2 * z2 + z3 * z3 * z3;
                }
            }
        }
        #pragma unroll
        for (int o = 16; o > 0; o >>= 1)
            part += __shfl_xor_sync(0xffffffffu, part, o);
        if (lid == 0) wred[it][wid] = part;
    }

    __syncthreads();                               // S-final

    // ---- phase 4: 2 softmaxes in parallel
    if (t < TPB) {
        const int key  = (t == 0) ? k0 : k1;
        const int tile = key & 1;
        float v0 = wred[t][0] + wred[t][1] + wred[t][4] + wred[t][5];   // c in [0,64)
        float v1 = wred[t][2] + wred[t][3] + wred[t][6] + wred[t][7];   // c in [64,128)
        float gate = s_gate[tile];
        float a0v = gate * v0, a1v = gate * v1;
        float m  = fmaxf(a0v, a1v);
        float e0 = expf(a0v - m), e1 = expf(a1v - m);
        float inv = 1.f / (e0 + e1);
        const int bo = blockIdx.x * TPB + tile;
        out[bo * 2 + 0] = e0 * inv;
        out[bo * 2 + 1] = e1 * inv;
    }

    // ---- loss finalization (last block), off everyone else's path
    if (t == 32) {
        __threadfence();
        unsigned int tk = atomicAdd(&g_ticket, 1u);
        if (tk == NBLK - 1) {
            __threadfence();
            double L = 0.0;
            #pragma unroll
            for (int e = 0; e < EE; e++) {
                unsigned long long sraw = atomicAdd(&g_lsum[e], 0ULL);
                int cc = atomicAdd(&g_cnt[e], 0);
                L += ((double)(long long)sraw * (1.0 / 4294967296.0)) * (double)cc;
            }
            if (full)
                out[BB * 2 + BB * EE] = (float)(L * (double)EE / ((double)BB * (double)BB));
            #pragma unroll
            for (int e = 0; e < EE; e++) {
                atomicExch(&g_lsum[e], 0ULL);
                atomicExch(&g_cnt[e], 0);
            }
            atomicExch(&g_ticket, 0u);
        }
    }
}

// ---------------------------------------------------------------------------
extern "C" void kernel_launch(void* const* d_in, const int* in_sizes, int n_in,
                              void* d_out, int out_size)
{
    const float* x  = (const float*)d_in[0];
    const float* rw = (const float*)d_in[1];
    const float* ew = (const float*)d_in[2];
    const float* eb = (const float*)d_in[3];
    float* out = (float*)d_out;

    const int full = (out_size >= BB * 2 + BB * EE + 1) ? 1 : 0;

    cudaFuncSetAttribute(moe_one, cudaFuncAttributeMaxDynamicSharedMemorySize, SM_TOTAL);
    cudaFuncSetAttribute(moe_one, cudaFuncAttributePreferredSharedMemoryCarveout, 100);
    moe_one<<<NBLK, NTHR, SM_TOTAL>>>(x, rw, ew, eb, out, full);
}